// round 12
// baseline (speedup 1.0000x reference)
#include <cuda_runtime.h>
#include <stdint.h>

// Problem constants (fixed shapes for this problem)
#define BB 8
#define MM 1000000
#define NN (BB*MM)
#define GG 32                       // GRID/STRIDE = 128/4
#define SEGB (GG*GG*GG)             // 32768 blocks per batch (fits uint16)
#define NSEG (BB*SEGB)              // 262144 coarse blocks
#define PPB 4096                    // points per tile
#define NCHUNK ((MM + PPB - 1)/PPB) // 245
#define CAND_CAP (1<<20)            // >= MM: overflow impossible

// Scratch (static device allocations only)
__device__ unsigned g_bm[NSEG];          // per-block max (ordered-uint)
__device__ unsigned short g_seg16[NN];   // per-point seg-within-batch
__device__ unsigned g_mask[NN/32];       // 4-bit nibbles: is local max
__device__ unsigned g_h1[BB*2048];       // raw level-1 hist (uncorrected)
__device__ unsigned g_h2[BB*2048];       // level-2 hist
__device__ unsigned g_prefix1[BB];       // 11-bit prefix after k_corr
__device__ unsigned g_krem1[BB];
__device__ unsigned g_prefix2[BB];       // 22-bit prefix after k_mask2
__device__ unsigned g_krem2[BB];
__device__ unsigned g_thr[BB];
__device__ unsigned g_ctr2[BB];
__device__ unsigned g_ccount[BB];
__device__ unsigned g_cand[BB*CAND_CAP];

// Order-preserving float <-> uint bijection (total order, strict monotone)
__device__ __forceinline__ unsigned f2o(float f){
    unsigned b = __float_as_uint(f);
    return (b & 0x80000000u) ? ~b : (b | 0x80000000u);
}

// ---------------------------------------------------------------- zero scratch
__global__ void k_zero(){
    int i = blockIdx.x*blockDim.x + threadIdx.x;
    int stride = gridDim.x*blockDim.x;
    for (int j = i; j < NSEG; j += stride) g_bm[j] = 0u;
    for (int j = i; j < BB*2048; j += stride){ g_h1[j] = 0u; g_h2[j] = 0u; }
    if (i < BB){ g_ctr2[i] = 0u; g_ccount[i] = 0u; }
}

// ---------- pass A: seg ids + block max + RAW level-1 histogram (fused)
__global__ void k_blockmax(const float* __restrict__ pred,
                           const int4*  __restrict__ coords){
    __shared__ unsigned sh[2048];
    for (int j = threadIdx.x; j < 2048; j += blockDim.x) sh[j] = 0u;
    __syncthreads();

    int b = blockIdx.y;
    int start = blockIdx.x * PPB;
    long base = (long)b * MM + start;
    const int4*   c4 = coords + base;
    const float4* p4 = (const float4*)pred + (base >> 2);
    ushort4*      s4 = (ushort4*)g_seg16 + (base >> 2);
    unsigned*    bmb = g_bm + b * SEGB;
    int nv = min(PPB, MM - start) >> 2;

    for (int v = threadIdx.x; v < nv; v += blockDim.x){
        int4 c0 = c4[4*v], c1 = c4[4*v+1], c2 = c4[4*v+2], c3 = c4[4*v+3];
        float4 p = p4[v];
        unsigned l0 = (((unsigned)c0.y>>2)*GG + ((unsigned)c0.z>>2))*GG + ((unsigned)c0.w>>2);
        unsigned l1 = (((unsigned)c1.y>>2)*GG + ((unsigned)c1.z>>2))*GG + ((unsigned)c1.w>>2);
        unsigned l2 = (((unsigned)c2.y>>2)*GG + ((unsigned)c2.z>>2))*GG + ((unsigned)c2.w>>2);
        unsigned l3 = (((unsigned)c3.y>>2)*GG + ((unsigned)c3.z>>2))*GG + ((unsigned)c3.w>>2);
        s4[v] = make_ushort4((unsigned short)l0, (unsigned short)l1,
                             (unsigned short)l2, (unsigned short)l3);
        unsigned f0 = f2o(p.x), f1 = f2o(p.y), f2 = f2o(p.z), f3 = f2o(p.w);
        atomicMax(&bmb[l0], f0);
        atomicMax(&bmb[l1], f1);
        atomicMax(&bmb[l2], f2);
        atomicMax(&bmb[l3], f3);
        atomicAdd(&sh[f0 >> 21], 1u);
        atomicAdd(&sh[f1 >> 21], 1u);
        atomicAdd(&sh[f2 >> 21], 1u);
        atomicAdd(&sh[f3 >> 21], 1u);
    }
    __syncthreads();
    unsigned* gh = g_h1 + b*2048;
    for (int j = threadIdx.x; j < 2048; j += blockDim.x){
        unsigned c = sh[j];
        if (c) atomicAdd(&gh[j], c);
    }
}

// ---- pass C: correct hist by block maxima (one masked point per nonempty seg)
//      then level-1 scan -> prefix1/krem1. One block per batch.
__global__ void k_corr(const int* __restrict__ tnum){
    __shared__ unsigned shh[2048];
    __shared__ unsigned partial[256];
    __shared__ unsigned excl[256];
    int b = blockIdx.x;
    for (int j = threadIdx.x; j < 2048; j += blockDim.x)
        shh[j] = __ldcg(&g_h1[b*2048 + j]);
    __syncthreads();
    const unsigned* bmb = g_bm + b * SEGB;
    for (int i = threadIdx.x; i < SEGB; i += blockDim.x){
        unsigned v = __ldcg(&bmb[i]);
        if (v) atomicSub(&shh[v >> 21], 1u);   // its masked point leaves this bin
    }
    __syncthreads();

    unsigned loc[8];
    unsigned s = 0;
    #pragma unroll
    for (int j = 0; j < 8; j++){ loc[j] = shh[threadIdx.x*8 + j]; s += loc[j]; }
    partial[threadIdx.x] = s;
    __syncthreads();
    if (threadIdx.x == 0){
        unsigned c = 0;
        for (int t = 0; t < 256; t++){ unsigned v = partial[t]; excl[t] = c; c += v; }
    }
    __syncthreads();
    unsigned krem = (unsigned)(MM - tnum[0]);
    unsigned cum = excl[threadIdx.x];
    #pragma unroll
    for (int j = 0; j < 8; j++){
        unsigned bin = threadIdx.x*8 + j;
        unsigned c = loc[j];
        if (cum < krem && cum + c >= krem){
            g_prefix1[b] = bin;
            g_krem1[b]   = krem - cum;
        }
        cum += c;
    }
}

// -- pass B: local-max bitmap + prefix1-filtered level-2 hist + compaction
//    (exact mask filtering; fused last-block level-2 scan)
__global__ void k_mask2(const float* __restrict__ pred){
    __shared__ unsigned sh[2048];
    __shared__ unsigned smb[PPB/32];
    __shared__ unsigned stage[PPB];
    __shared__ unsigned scount, sbase;
    __shared__ int isLast;
    for (int j = threadIdx.x; j < 2048; j += blockDim.x) sh[j] = 0u;
    if (threadIdx.x < PPB/32) smb[threadIdx.x] = 0u;
    if (threadIdx.x == 0) scount = 0u;
    __syncthreads();

    int b = blockIdx.y;
    unsigned p1 = g_prefix1[b];
    int start = blockIdx.x * PPB;
    long base = (long)b * MM + start;
    const ushort4* s4 = (const ushort4*)g_seg16 + (base >> 2);
    const float4*  p4 = (const float4*)pred + (base >> 2);
    const unsigned* bmb = g_bm + b * SEGB;
    int nv = min(PPB, MM - start) >> 2;

    for (int v = threadIdx.x; v < nv; v += blockDim.x){
        ushort4 s = s4[v];
        float4 p = p4[v];
        unsigned fx = f2o(p.x), fy = f2o(p.y), fz = f2o(p.z), fw = f2o(p.w);
        unsigned mx = (fx == bmb[s.x]);
        unsigned my = (fy == bmb[s.y]);
        unsigned mz = (fz == bmb[s.z]);
        unsigned mw = (fw == bmb[s.w]);
        unsigned nib = mx | (my << 1) | (mz << 2) | (mw << 3);
        if (nib) atomicOr(&smb[v >> 3], nib << ((v & 7) * 4));
        if (!mx && (fx >> 21) == p1){ atomicAdd(&sh[(fx >> 10) & 2047u], 1u);
                                      stage[atomicAdd(&scount, 1u)] = fx; }
        if (!my && (fy >> 21) == p1){ atomicAdd(&sh[(fy >> 10) & 2047u], 1u);
                                      stage[atomicAdd(&scount, 1u)] = fy; }
        if (!mz && (fz >> 21) == p1){ atomicAdd(&sh[(fz >> 10) & 2047u], 1u);
                                      stage[atomicAdd(&scount, 1u)] = fz; }
        if (!mw && (fw >> 21) == p1){ atomicAdd(&sh[(fw >> 10) & 2047u], 1u);
                                      stage[atomicAdd(&scount, 1u)] = fw; }
    }
    __syncthreads();

    // flush ONLY the bitmap words owned by this tile (no cross-batch clobber)
    int nwords = (nv + 7) >> 3;
    unsigned* gw = g_mask + (base >> 5);
    if (threadIdx.x < nwords) gw[threadIdx.x] = smb[threadIdx.x];

    // one global reservation per block, then coalesced candidate flush
    if (threadIdx.x == 0) sbase = atomicAdd(&g_ccount[b], scount);
    __syncthreads();
    unsigned* cand = g_cand + (size_t)b * CAND_CAP;
    for (unsigned i = threadIdx.x; i < scount; i += blockDim.x)
        __stcg(&cand[sbase + i], stage[i]);

    unsigned* gh = g_h2 + b*2048;
    for (int j = threadIdx.x; j < 2048; j += blockDim.x){
        unsigned c = sh[j];
        if (c) atomicAdd(&gh[j], c);
    }
    __threadfence();
    if (threadIdx.x == 0)
        isLast = (atomicAdd(&g_ctr2[b], 1u) == (unsigned)(NCHUNK - 1));
    __syncthreads();
    if (!isLast) return;

    // ---- level-2 scan over g_h2 -> prefix2 (22 bit) + krem2 ----
    __shared__ unsigned partial[256];
    __shared__ unsigned excl[256];
    unsigned loc[8];
    unsigned s = 0;
    #pragma unroll
    for (int j = 0; j < 8; j++){ loc[j] = __ldcg(&gh[threadIdx.x*8 + j]); s += loc[j]; }
    partial[threadIdx.x] = s;
    __syncthreads();
    if (threadIdx.x == 0){
        unsigned c = 0;
        for (int t = 0; t < 256; t++){ unsigned v = partial[t]; excl[t] = c; c += v; }
    }
    __syncthreads();
    unsigned krem = g_krem1[b];
    unsigned cum = excl[threadIdx.x];
    #pragma unroll
    for (int j = 0; j < 8; j++){
        unsigned bin = threadIdx.x*8 + j;
        unsigned c = loc[j];
        if (cum < krem && cum + c >= krem){
            g_prefix2[b] = (p1 << 11) | bin;
            g_krem2[b]   = krem - cum;
        }
        cum += c;
    }
}

// ------ pass D: candidates only (one block per batch), in-shared hist + scan
__global__ void k_hist3(){
    __shared__ unsigned sh[1024];
    __shared__ unsigned partial[256];
    __shared__ unsigned excl[256];
    int b = blockIdx.x;
    for (int j = threadIdx.x; j < 1024; j += blockDim.x) sh[j] = 0u;
    __syncthreads();

    unsigned p22 = g_prefix2[b];
    unsigned n = min(g_ccount[b], (unsigned)CAND_CAP);
    const unsigned* cand = g_cand + (size_t)b * CAND_CAP;
    for (unsigned i = threadIdx.x; i < n; i += blockDim.x){
        unsigned k = __ldcg(&cand[i]);
        if ((k >> 10) == p22) atomicAdd(&sh[k & 1023u], 1u);
    }
    __syncthreads();

    unsigned loc[4];
    unsigned s = 0;
    #pragma unroll
    for (int j = 0; j < 4; j++){ loc[j] = sh[threadIdx.x*4 + j]; s += loc[j]; }
    partial[threadIdx.x] = s;
    __syncthreads();
    if (threadIdx.x == 0){
        unsigned c = 0;
        for (int t = 0; t < 256; t++){ unsigned v = partial[t]; excl[t] = c; c += v; }
    }
    __syncthreads();
    unsigned krem = g_krem2[b];
    unsigned cum = excl[threadIdx.x];
    #pragma unroll
    for (int j = 0; j < 4; j++){
        unsigned bin = threadIdx.x*4 + j;
        unsigned c = loc[j];
        if (cum < krem && cum + c >= krem)
            g_thr[b] = (p22 << 10) | bin;      // kth-smallest key
        cum += c;
    }
}

// -------------------------------------------------------- final masked output
__global__ void k_out(const float* __restrict__ pred, float* __restrict__ out){
    int v = blockIdx.x*blockDim.x + threadIdx.x;   // vector index, NN/4 total
    if (v >= NN/4) return;
    int b = v / (MM/4);
    unsigned thr = g_thr[b];
    unsigned nib = (__ldcg(&g_mask[v >> 3]) >> ((v & 7) * 4)) & 0xFu;
    float4 p = ((const float4*)pred)[v];
    float4 o;
    o.x = ((nib & 1u) || f2o(p.x) > thr) ? p.x : 0.0f;
    o.y = ((nib & 2u) || f2o(p.y) > thr) ? p.y : 0.0f;
    o.z = ((nib & 4u) || f2o(p.z) > thr) ? p.z : 0.0f;
    o.w = ((nib & 8u) || f2o(p.w) > thr) ? p.w : 0.0f;
    __stcs(&((float4*)out)[v], o);
}

extern "C" void kernel_launch(void* const* d_in, const int* in_sizes, int n_in,
                              void* d_out, int out_size){
    const float* pred   = (const float*)d_in[0];
    const int4*  coords = (const int4*)d_in[1];
    const int*   tnum   = (const int*)d_in[2];
    float* out = (float*)d_out;

    dim3 gh(NCHUNK, BB);
    k_zero<<<512, 256>>>();
    k_blockmax<<<gh, 256>>>(pred, coords);
    k_corr<<<BB, 256>>>(tnum);
    k_mask2<<<gh, 256>>>(pred);
    k_hist3<<<BB, 256>>>();
    k_out<<<(NN/4 + 255)/256, 256>>>(pred, out);
}

// round 14
// speedup vs baseline: 1.1087x; 1.1087x over previous
#include <cuda_runtime.h>
#include <stdint.h>

// Problem constants (fixed shapes for this problem)
#define BB 8
#define MM 1000000
#define NN (BB*MM)
#define GG 32                       // GRID/STRIDE = 128/4
#define SEGB (GG*GG*GG)             // 32768 blocks per batch
#define NSEG (BB*SEGB)              // 262144 coarse blocks
#define PPB 4096                    // points per tile
#define NCHUNK ((MM + PPB - 1)/PPB) // 245
#define CAND_CAP (1<<20)            // >= MM: overflow impossible
#define NMASKW (NN/32)              // 250000 mask words

// Scratch (static device allocations only)
__device__ unsigned long long g_bm64[NSEG]; // per-seg packed (max_key<<32 | idx)
__device__ unsigned g_mask[NMASKW];      // 1 bit per point: is seg winner
__device__ unsigned g_h1[BB*2048];       // raw level-1 hist (uncorrected)
__device__ unsigned g_h2[BB*2048];       // level-2 hist
__device__ unsigned g_prefix1[BB];       // 11-bit prefix after k_corr
__device__ unsigned g_krem1[BB];
__device__ unsigned g_prefix2[BB];       // 22-bit prefix after k_hist2
__device__ unsigned g_krem2[BB];
__device__ unsigned g_thr[BB];
__device__ unsigned g_ctr2[BB];
__device__ unsigned g_ccount[BB];
__device__ unsigned g_cand[BB*CAND_CAP];

// Order-preserving float <-> uint bijection (total order, strict monotone)
__device__ __forceinline__ unsigned f2o(float f){
    unsigned b = __float_as_uint(f);
    return (b & 0x80000000u) ? ~b : (b | 0x80000000u);
}

// ---------------------------------------------------------------- zero scratch
__global__ void k_zero(){
    int i = blockIdx.x*blockDim.x + threadIdx.x;
    int stride = gridDim.x*blockDim.x;
    for (int j = i; j < NSEG; j += stride) g_bm64[j] = 0ull;
    for (int j = i; j < NMASKW; j += stride) g_mask[j] = 0u;
    for (int j = i; j < BB*2048; j += stride){ g_h1[j] = 0u; g_h2[j] = 0u; }
    if (i < BB){ g_ctr2[i] = 0u; g_ccount[i] = 0u; }
}

// ---------- pass A: per-seg argmax (packed 64-bit) + RAW level-1 histogram
__global__ void k_blockmax(const float* __restrict__ pred,
                           const int4*  __restrict__ coords){
    __shared__ unsigned sh[2048];
    for (int j = threadIdx.x; j < 2048; j += blockDim.x) sh[j] = 0u;
    __syncthreads();

    int b = blockIdx.y;
    int start = blockIdx.x * PPB;
    long base = (long)b * MM + start;
    const int4*   c4 = coords + base;
    const float4* p4 = (const float4*)pred + (base >> 2);
    unsigned long long* bmb = g_bm64 + b * SEGB;
    int nv = min(PPB, MM - start) >> 2;

    for (int v = threadIdx.x; v < nv; v += blockDim.x){
        int4 c0 = c4[4*v], c1 = c4[4*v+1], c2 = c4[4*v+2], c3 = c4[4*v+3];
        float4 p = p4[v];
        unsigned l0 = (((unsigned)c0.y>>2)*GG + ((unsigned)c0.z>>2))*GG + ((unsigned)c0.w>>2);
        unsigned l1 = (((unsigned)c1.y>>2)*GG + ((unsigned)c1.z>>2))*GG + ((unsigned)c1.w>>2);
        unsigned l2 = (((unsigned)c2.y>>2)*GG + ((unsigned)c2.z>>2))*GG + ((unsigned)c2.w>>2);
        unsigned l3 = (((unsigned)c3.y>>2)*GG + ((unsigned)c3.z>>2))*GG + ((unsigned)c3.w>>2);
        unsigned f0 = f2o(p.x), f1 = f2o(p.y), f2 = f2o(p.z), f3 = f2o(p.w);
        unsigned i0 = (unsigned)(start + 4*v);      // idx within batch
        atomicMax(&bmb[l0], ((unsigned long long)f0 << 32) | i0);
        atomicMax(&bmb[l1], ((unsigned long long)f1 << 32) | (i0+1));
        atomicMax(&bmb[l2], ((unsigned long long)f2 << 32) | (i0+2));
        atomicMax(&bmb[l3], ((unsigned long long)f3 << 32) | (i0+3));
        atomicAdd(&sh[f0 >> 21], 1u);
        atomicAdd(&sh[f1 >> 21], 1u);
        atomicAdd(&sh[f2 >> 21], 1u);
        atomicAdd(&sh[f3 >> 21], 1u);
    }
    __syncthreads();
    unsigned* gh = g_h1 + b*2048;
    for (int j = threadIdx.x; j < 2048; j += blockDim.x){
        unsigned c = sh[j];
        if (c) atomicAdd(&gh[j], c);
    }
}

// ---- pass C: hist correction + winner-bit scatter + level-1 scan.
//      One block per batch (8 blocks total).
__global__ void k_corr(const int* __restrict__ tnum){
    __shared__ unsigned shh[2048];
    __shared__ unsigned partial[256];
    __shared__ unsigned excl[256];
    int b = blockIdx.x;
    for (int j = threadIdx.x; j < 2048; j += blockDim.x)
        shh[j] = __ldcg(&g_h1[b*2048 + j]);
    __syncthreads();
    const unsigned long long* bmb = g_bm64 + b * SEGB;
    for (int i = threadIdx.x; i < SEGB; i += blockDim.x){
        unsigned long long v = __ldcg(&bmb[i]);
        if (v){
            unsigned key = (unsigned)(v >> 32);
            atomicSub(&shh[key >> 21], 1u);        // winner leaves its bin
            long gidx = (long)b * MM + (unsigned)v; // winner's global index
            atomicOr(&g_mask[gidx >> 5], 1u << ((unsigned)gidx & 31u));
        }
    }
    __syncthreads();

    unsigned loc[8];
    unsigned s = 0;
    #pragma unroll
    for (int j = 0; j < 8; j++){ loc[j] = shh[threadIdx.x*8 + j]; s += loc[j]; }
    partial[threadIdx.x] = s;
    __syncthreads();
    if (threadIdx.x == 0){
        unsigned c = 0;
        for (int t = 0; t < 256; t++){ unsigned v = partial[t]; excl[t] = c; c += v; }
    }
    __syncthreads();
    unsigned krem = (unsigned)(MM - tnum[0]);
    unsigned cum = excl[threadIdx.x];
    #pragma unroll
    for (int j = 0; j < 8; j++){
        unsigned bin = threadIdx.x*8 + j;
        unsigned c = loc[j];
        if (cum < krem && cum + c >= krem){
            g_prefix1[b] = bin;
            g_krem1[b]   = krem - cum;
        }
        cum += c;
    }
}

// -- pass 2: prefix1-filtered level-2 hist + staged compaction + fused scan
//    (no gathers: mask comes from the bitmap)
__global__ void k_hist2(const float* __restrict__ pred){
    __shared__ unsigned sh[2048];
    __shared__ unsigned stage[PPB];
    __shared__ unsigned scount, sbase;
    __shared__ int isLast;
    for (int j = threadIdx.x; j < 2048; j += blockDim.x) sh[j] = 0u;
    if (threadIdx.x == 0) scount = 0u;
    __syncthreads();

    int b = blockIdx.y;
    unsigned p1 = g_prefix1[b];
    int start = blockIdx.x * PPB;
    long base = (long)b * MM + start;
    const float4* p4 = (const float4*)pred + (base >> 2);
    const unsigned* gw = g_mask + (base >> 5);
    int nv = min(PPB, MM - start) >> 2;

    for (int v = threadIdx.x; v < nv; v += blockDim.x){
        float4 pv = p4[v];
        unsigned nib = (__ldcg(&gw[v >> 3]) >> ((v & 7) * 4)) & 0xFu;
        unsigned fx = f2o(pv.x), fy = f2o(pv.y), fz = f2o(pv.z), fw = f2o(pv.w);
        if (!(nib & 1u) && (fx >> 21) == p1){ atomicAdd(&sh[(fx >> 10) & 2047u], 1u);
                                              stage[atomicAdd(&scount, 1u)] = fx; }
        if (!(nib & 2u) && (fy >> 21) == p1){ atomicAdd(&sh[(fy >> 10) & 2047u], 1u);
                                              stage[atomicAdd(&scount, 1u)] = fy; }
        if (!(nib & 4u) && (fz >> 21) == p1){ atomicAdd(&sh[(fz >> 10) & 2047u], 1u);
                                              stage[atomicAdd(&scount, 1u)] = fz; }
        if (!(nib & 8u) && (fw >> 21) == p1){ atomicAdd(&sh[(fw >> 10) & 2047u], 1u);
                                              stage[atomicAdd(&scount, 1u)] = fw; }
    }
    __syncthreads();

    // one global reservation per block, then coalesced candidate flush
    if (threadIdx.x == 0) sbase = atomicAdd(&g_ccount[b], scount);
    __syncthreads();
    unsigned* cand = g_cand + (size_t)b * CAND_CAP;
    for (unsigned i = threadIdx.x; i < scount; i += blockDim.x)
        __stcg(&cand[sbase + i], stage[i]);

    unsigned* gh = g_h2 + b*2048;
    for (int j = threadIdx.x; j < 2048; j += blockDim.x){
        unsigned c = sh[j];
        if (c) atomicAdd(&gh[j], c);
    }
    __threadfence();
    if (threadIdx.x == 0)
        isLast = (atomicAdd(&g_ctr2[b], 1u) == (unsigned)(NCHUNK - 1));
    __syncthreads();
    if (!isLast) return;

    // ---- level-2 scan over g_h2 -> prefix2 (22 bit) + krem2 ----
    __shared__ unsigned partial[256];
    __shared__ unsigned excl[256];
    unsigned loc[8];
    unsigned s = 0;
    #pragma unroll
    for (int j = 0; j < 8; j++){ loc[j] = __ldcg(&gh[threadIdx.x*8 + j]); s += loc[j]; }
    partial[threadIdx.x] = s;
    __syncthreads();
    if (threadIdx.x == 0){
        unsigned c = 0;
        for (int t = 0; t < 256; t++){ unsigned v = partial[t]; excl[t] = c; c += v; }
    }
    __syncthreads();
    unsigned krem = g_krem1[b];
    unsigned cum = excl[threadIdx.x];
    #pragma unroll
    for (int j = 0; j < 8; j++){
        unsigned bin = threadIdx.x*8 + j;
        unsigned c = loc[j];
        if (cum < krem && cum + c >= krem){
            g_prefix2[b] = (p1 << 11) | bin;
            g_krem2[b]   = krem - cum;
        }
        cum += c;
    }
}

// ------ pass D: candidates only (one block per batch), in-shared hist + scan
__global__ void k_hist3(){
    __shared__ unsigned sh[1024];
    __shared__ unsigned partial[256];
    __shared__ unsigned excl[256];
    int b = blockIdx.x;
    for (int j = threadIdx.x; j < 1024; j += blockDim.x) sh[j] = 0u;
    __syncthreads();

    unsigned p22 = g_prefix2[b];
    unsigned n = min(g_ccount[b], (unsigned)CAND_CAP);
    const unsigned* cand = g_cand + (size_t)b * CAND_CAP;
    for (unsigned i = threadIdx.x; i < n; i += blockDim.x){
        unsigned k = __ldcg(&cand[i]);
        if ((k >> 10) == p22) atomicAdd(&sh[k & 1023u], 1u);
    }
    __syncthreads();

    unsigned loc[4];
    unsigned s = 0;
    #pragma unroll
    for (int j = 0; j < 4; j++){ loc[j] = sh[threadIdx.x*4 + j]; s += loc[j]; }
    partial[threadIdx.x] = s;
    __syncthreads();
    if (threadIdx.x == 0){
        unsigned c = 0;
        for (int t = 0; t < 256; t++){ unsigned v = partial[t]; excl[t] = c; c += v; }
    }
    __syncthreads();
    unsigned krem = g_krem2[b];
    unsigned cum = excl[threadIdx.x];
    #pragma unroll
    for (int j = 0; j < 4; j++){
        unsigned bin = threadIdx.x*4 + j;
        unsigned c = loc[j];
        if (cum < krem && cum + c >= krem)
            g_thr[b] = (p22 << 10) | bin;      // kth-smallest key
        cum += c;
    }
}

// -------------------------------------------------------- final masked output
__global__ void k_out(const float* __restrict__ pred, float* __restrict__ out){
    int v = blockIdx.x*blockDim.x + threadIdx.x;   // vector index, NN/4 total
    if (v >= NN/4) return;
    int b = v / (MM/4);
    unsigned thr = g_thr[b];
    unsigned nib = (__ldcg(&g_mask[v >> 3]) >> ((v & 7) * 4)) & 0xFu;
    float4 p = ((const float4*)pred)[v];
    float4 o;
    o.x = ((nib & 1u) || f2o(p.x) > thr) ? p.x : 0.0f;
    o.y = ((nib & 2u) || f2o(p.y) > thr) ? p.y : 0.0f;
    o.z = ((nib & 4u) || f2o(p.z) > thr) ? p.z : 0.0f;
    o.w = ((nib & 8u) || f2o(p.w) > thr) ? p.w : 0.0f;
    __stcs(&((float4*)out)[v], o);
}

extern "C" void kernel_launch(void* const* d_in, const int* in_sizes, int n_in,
                              void* d_out, int out_size){
    const float* pred   = (const float*)d_in[0];
    const int4*  coords = (const int4*)d_in[1];
    const int*   tnum   = (const int*)d_in[2];
    float* out = (float*)d_out;

    dim3 gh(NCHUNK, BB);
    k_zero<<<512, 256>>>();
    k_blockmax<<<gh, 256>>>(pred, coords);
    k_corr<<<BB, 256>>>(tnum);
    k_hist2<<<gh, 256>>>(pred);
    k_hist3<<<BB, 256>>>();
    k_out<<<(NN/4 + 255)/256, 256>>>(pred, out);
}

// round 15
// speedup vs baseline: 1.2427x; 1.1209x over previous
#include <cuda_runtime.h>
#include <stdint.h>

// Problem constants (fixed shapes for this problem)
#define BB 8
#define MM 1000000
#define NN (BB*MM)
#define GG 32                       // GRID/STRIDE = 128/4
#define SEGB (GG*GG*GG)             // 32768 blocks per batch (fits uint16)
#define NSEG (BB*SEGB)              // 262144 coarse blocks
#define PPB 4096                    // points per tile (hist2)
#define NCHUNK ((MM + PPB - 1)/PPB) // 245
#define CAND_CAP (1<<20)            // >= MM: overflow impossible
#define WPB 31250                   // mask words per batch (MM/32, exact)
#define NMASKW (BB*WPB)

// Scratch (static device allocations only)
__device__ unsigned g_bm[NSEG];          // per-seg max key (ordered-uint)
__device__ unsigned short g_seg16[NN];   // per-point seg-within-batch
__device__ unsigned g_mask[NMASKW];      // 1 bit per point: is local max
__device__ unsigned g_h1[BB*2048];       // raw level-1 hist (uncorrected)
__device__ unsigned g_h2[BB*2048];       // level-2 hist
__device__ unsigned g_prefix1[BB];       // 11-bit prefix after k_corr
__device__ unsigned g_krem1[BB];
__device__ unsigned g_prefix2[BB];       // 22-bit prefix after k_hist2
__device__ unsigned g_krem2[BB];
__device__ unsigned g_thr[BB];
__device__ unsigned g_ctr2[BB];
__device__ unsigned g_ccount[BB];
__device__ unsigned g_cand[BB*CAND_CAP];

// Order-preserving float <-> uint bijection (total order, strict monotone)
__device__ __forceinline__ unsigned f2o(float f){
    unsigned b = __float_as_uint(f);
    return (b & 0x80000000u) ? ~b : (b | 0x80000000u);
}

// ---------------------------------------------------------------- zero scratch
__global__ void k_zero(){
    int i = blockIdx.x*blockDim.x + threadIdx.x;
    int stride = gridDim.x*blockDim.x;
    for (int j = i; j < NSEG; j += stride) g_bm[j] = 0u;
    for (int j = i; j < BB*2048; j += stride){ g_h1[j] = 0u; g_h2[j] = 0u; }
    if (i < BB){ g_ctr2[i] = 0u; g_ccount[i] = 0u; }
}

// -------- pass A: seg ids + 32-bit block max (coalesced scalar per point)
__global__ void k_blockmax(const float* __restrict__ pred,
                           const int4*  __restrict__ coords){
    int i = blockIdx.x*blockDim.x + threadIdx.x;
    int stride = gridDim.x*blockDim.x;
    for (int j = i; j < NN; j += stride){
        int4 c = coords[j];   // (batch, x, y, z) — coalesced LDG.128
        unsigned local = (((unsigned)c.y >> 2) * GG + ((unsigned)c.z >> 2)) * GG
                         + ((unsigned)c.w >> 2);
        g_seg16[j] = (unsigned short)local;
        atomicMax(&g_bm[(unsigned)c.x * SEGB + local], f2o(pred[j]));
    }
}

// ---- pass B: winner bitmap (1 thread per 32-pt word, no mask atomics)
//      + raw level-1 histogram (shared)
__global__ void k_wmask(const float* __restrict__ pred){
    __shared__ unsigned sh[2048];
    for (int j = threadIdx.x; j < 2048; j += blockDim.x) sh[j] = 0u;
    __syncthreads();

    int b = blockIdx.y;
    int w = blockIdx.x*blockDim.x + threadIdx.x;   // word within batch
    const unsigned* bmb = g_bm + b * SEGB;
    if (w < WPB){
        long p0 = (long)b * MM + (long)w * 32;     // first point of this word
        const float4*  p4 = (const float4*)pred + (p0 >> 2);
        const ushort4* s4 = (const ushort4*)g_seg16 + (p0 >> 2);
        unsigned word = 0u;
        #pragma unroll
        for (int c = 0; c < 8; c++){               // 8 chunks of 4 points
            float4  p = p4[c];
            ushort4 s = s4[c];
            unsigned f0 = f2o(p.x), f1 = f2o(p.y), f2 = f2o(p.z), f3 = f2o(p.w);
            word |= (unsigned)(f0 == bmb[s.x]) << (c*4 + 0);
            word |= (unsigned)(f1 == bmb[s.y]) << (c*4 + 1);
            word |= (unsigned)(f2 == bmb[s.z]) << (c*4 + 2);
            word |= (unsigned)(f3 == bmb[s.w]) << (c*4 + 3);
            atomicAdd(&sh[f0 >> 21], 1u);
            atomicAdd(&sh[f1 >> 21], 1u);
            atomicAdd(&sh[f2 >> 21], 1u);
            atomicAdd(&sh[f3 >> 21], 1u);
        }
        g_mask[(long)b * WPB + w] = word;          // plain coalesced store
    }
    __syncthreads();
    unsigned* gh = g_h1 + b*2048;
    for (int j = threadIdx.x; j < 2048; j += blockDim.x){
        unsigned c = sh[j];
        if (c) atomicAdd(&gh[j], c);
    }
}

// ---- pass C: hist correction (1 masked point per nonempty seg) + level-1 scan
__global__ void k_corr(const int* __restrict__ tnum){
    __shared__ unsigned shh[2048];
    __shared__ unsigned partial[256];
    __shared__ unsigned excl[256];
    int b = blockIdx.x;
    for (int j = threadIdx.x; j < 2048; j += blockDim.x)
        shh[j] = __ldcg(&g_h1[b*2048 + j]);
    __syncthreads();
    const unsigned* bmb = g_bm + b * SEGB;
    for (int i = threadIdx.x; i < SEGB; i += blockDim.x){
        unsigned v = __ldcg(&bmb[i]);
        if (v) atomicSub(&shh[v >> 21], 1u);       // its masked point leaves bin
    }
    __syncthreads();

    unsigned loc[8];
    unsigned s = 0;
    #pragma unroll
    for (int j = 0; j < 8; j++){ loc[j] = shh[threadIdx.x*8 + j]; s += loc[j]; }
    partial[threadIdx.x] = s;
    __syncthreads();
    if (threadIdx.x == 0){
        unsigned c = 0;
        for (int t = 0; t < 256; t++){ unsigned v = partial[t]; excl[t] = c; c += v; }
    }
    __syncthreads();
    unsigned krem = (unsigned)(MM - tnum[0]);
    unsigned cum = excl[threadIdx.x];
    #pragma unroll
    for (int j = 0; j < 8; j++){
        unsigned bin = threadIdx.x*8 + j;
        unsigned c = loc[j];
        if (cum < krem && cum + c >= krem){
            g_prefix1[b] = bin;
            g_krem1[b]   = krem - cum;
        }
        cum += c;
    }
}

// -- pass 2: prefix1-filtered level-2 hist + staged compaction + fused scan
__global__ void k_hist2(const float* __restrict__ pred){
    __shared__ unsigned sh[2048];
    __shared__ unsigned stage[PPB];
    __shared__ unsigned scount, sbase;
    __shared__ int isLast;
    for (int j = threadIdx.x; j < 2048; j += blockDim.x) sh[j] = 0u;
    if (threadIdx.x == 0) scount = 0u;
    __syncthreads();

    int b = blockIdx.y;
    unsigned p1 = g_prefix1[b];
    int start = blockIdx.x * PPB;
    long base = (long)b * MM + start;
    const float4* p4 = (const float4*)pred + (base >> 2);
    const unsigned* gw = g_mask + (base >> 5);
    int nv = min(PPB, MM - start) >> 2;

    for (int v = threadIdx.x; v < nv; v += blockDim.x){
        float4 pv = p4[v];
        unsigned nib = (__ldcg(&gw[v >> 3]) >> ((v & 7) * 4)) & 0xFu;
        unsigned fx = f2o(pv.x), fy = f2o(pv.y), fz = f2o(pv.z), fw = f2o(pv.w);
        if (!(nib & 1u) && (fx >> 21) == p1){ atomicAdd(&sh[(fx >> 10) & 2047u], 1u);
                                              stage[atomicAdd(&scount, 1u)] = fx; }
        if (!(nib & 2u) && (fy >> 21) == p1){ atomicAdd(&sh[(fy >> 10) & 2047u], 1u);
                                              stage[atomicAdd(&scount, 1u)] = fy; }
        if (!(nib & 4u) && (fz >> 21) == p1){ atomicAdd(&sh[(fz >> 10) & 2047u], 1u);
                                              stage[atomicAdd(&scount, 1u)] = fz; }
        if (!(nib & 8u) && (fw >> 21) == p1){ atomicAdd(&sh[(fw >> 10) & 2047u], 1u);
                                              stage[atomicAdd(&scount, 1u)] = fw; }
    }
    __syncthreads();

    // one global reservation per block, then coalesced candidate flush
    if (threadIdx.x == 0) sbase = atomicAdd(&g_ccount[b], scount);
    __syncthreads();
    unsigned* cand = g_cand + (size_t)b * CAND_CAP;
    for (unsigned i = threadIdx.x; i < scount; i += blockDim.x)
        __stcg(&cand[sbase + i], stage[i]);

    unsigned* gh = g_h2 + b*2048;
    for (int j = threadIdx.x; j < 2048; j += blockDim.x){
        unsigned c = sh[j];
        if (c) atomicAdd(&gh[j], c);
    }
    __threadfence();
    if (threadIdx.x == 0)
        isLast = (atomicAdd(&g_ctr2[b], 1u) == (unsigned)(NCHUNK - 1));
    __syncthreads();
    if (!isLast) return;

    // ---- level-2 scan over g_h2 -> prefix2 (22 bit) + krem2 ----
    __shared__ unsigned partial[256];
    __shared__ unsigned excl[256];
    unsigned loc[8];
    unsigned s = 0;
    #pragma unroll
    for (int j = 0; j < 8; j++){ loc[j] = __ldcg(&gh[threadIdx.x*8 + j]); s += loc[j]; }
    partial[threadIdx.x] = s;
    __syncthreads();
    if (threadIdx.x == 0){
        unsigned c = 0;
        for (int t = 0; t < 256; t++){ unsigned v = partial[t]; excl[t] = c; c += v; }
    }
    __syncthreads();
    unsigned krem = g_krem1[b];
    unsigned cum = excl[threadIdx.x];
    #pragma unroll
    for (int j = 0; j < 8; j++){
        unsigned bin = threadIdx.x*8 + j;
        unsigned c = loc[j];
        if (cum < krem && cum + c >= krem){
            g_prefix2[b] = (p1 << 11) | bin;
            g_krem2[b]   = krem - cum;
        }
        cum += c;
    }
}

// ------ pass D: candidates only (one block per batch), in-shared hist + scan
__global__ void k_hist3(){
    __shared__ unsigned sh[1024];
    __shared__ unsigned partial[256];
    __shared__ unsigned excl[256];
    int b = blockIdx.x;
    for (int j = threadIdx.x; j < 1024; j += blockDim.x) sh[j] = 0u;
    __syncthreads();

    unsigned p22 = g_prefix2[b];
    unsigned n = min(g_ccount[b], (unsigned)CAND_CAP);
    const unsigned* cand = g_cand + (size_t)b * CAND_CAP;
    for (unsigned i = threadIdx.x; i < n; i += blockDim.x){
        unsigned k = __ldcg(&cand[i]);
        if ((k >> 10) == p22) atomicAdd(&sh[k & 1023u], 1u);
    }
    __syncthreads();

    unsigned loc[4];
    unsigned s = 0;
    #pragma unroll
    for (int j = 0; j < 4; j++){ loc[j] = sh[threadIdx.x*4 + j]; s += loc[j]; }
    partial[threadIdx.x] = s;
    __syncthreads();
    if (threadIdx.x == 0){
        unsigned c = 0;
        for (int t = 0; t < 256; t++){ unsigned v = partial[t]; excl[t] = c; c += v; }
    }
    __syncthreads();
    unsigned krem = g_krem2[b];
    unsigned cum = excl[threadIdx.x];
    #pragma unroll
    for (int j = 0; j < 4; j++){
        unsigned bin = threadIdx.x*4 + j;
        unsigned c = loc[j];
        if (cum < krem && cum + c >= krem)
            g_thr[b] = (p22 << 10) | bin;      // kth-smallest key
        cum += c;
    }
}

// -------------------------------------------------------- final masked output
__global__ void k_out(const float* __restrict__ pred, float* __restrict__ out){
    int v = blockIdx.x*blockDim.x + threadIdx.x;   // vector index, NN/4 total
    if (v >= NN/4) return;
    int b = v / (MM/4);
    unsigned thr = g_thr[b];
    unsigned nib = (__ldcg(&g_mask[v >> 3]) >> ((v & 7) * 4)) & 0xFu;
    float4 p = ((const float4*)pred)[v];
    float4 o;
    o.x = ((nib & 1u) || f2o(p.x) > thr) ? p.x : 0.0f;
    o.y = ((nib & 2u) || f2o(p.y) > thr) ? p.y : 0.0f;
    o.z = ((nib & 4u) || f2o(p.z) > thr) ? p.z : 0.0f;
    o.w = ((nib & 8u) || f2o(p.w) > thr) ? p.w : 0.0f;
    __stcs(&((float4*)out)[v], o);
}

extern "C" void kernel_launch(void* const* d_in, const int* in_sizes, int n_in,
                              void* d_out, int out_size){
    const float* pred   = (const float*)d_in[0];
    const int4*  coords = (const int4*)d_in[1];
    const int*   tnum   = (const int*)d_in[2];
    float* out = (float*)d_out;

    k_zero<<<512, 256>>>();
    k_blockmax<<<(NN + 511)/512, 256>>>(pred, coords);

    dim3 gw((WPB + 255)/256, BB);                  // 123 x 8 blocks
    k_wmask<<<gw, 256>>>(pred);
    k_corr<<<BB, 256>>>(tnum);

    dim3 gh(NCHUNK, BB);
    k_hist2<<<gh, 256>>>(pred);
    k_hist3<<<BB, 256>>>();
    k_out<<<(NN/4 + 255)/256, 256>>>(pred, out);
}

// round 16
// speedup vs baseline: 1.3244x; 1.0657x over previous
#include <cuda_runtime.h>
#include <stdint.h>

// Problem constants (fixed shapes for this problem)
#define BB 8
#define MM 1000000
#define NN (BB*MM)
#define GG 32                       // GRID/STRIDE = 128/4
#define SEGB (GG*GG*GG)             // 32768 blocks per batch (fits uint16)
#define NSEG (BB*SEGB)              // 262144 coarse blocks
#define PPB 4096                    // points per tile (hist2)
#define NCHUNK ((MM + PPB - 1)/PPB) // 245
#define CAND_CAP (1<<20)            // >= MM: overflow impossible
#define WPB 31250                   // mask words per batch (MM/32, exact)
#define NMASKW (BB*WPB)
#define WBLK ((WPB + 255)/256)      // 123 wmask blocks per batch
#define SEGSLICE ((SEGB + WBLK - 1)/WBLK)  // 267 segs per wmask block

// Scratch (static device allocations only)
__device__ unsigned g_bm[NSEG];          // per-seg max key (ordered-uint)
__device__ unsigned short g_seg16[NN];   // per-point seg-within-batch
__device__ unsigned g_mask[NMASKW];      // 1 bit per point: is local max
__device__ unsigned g_h1[BB*2048];       // corrected level-1 hist
__device__ unsigned g_h2[BB*2048];       // level-2 hist
__device__ unsigned g_prefix1[BB];       // 11-bit prefix after wmask scan
__device__ unsigned g_krem1[BB];
__device__ unsigned g_prefix2[BB];       // 22-bit prefix after k_hist2
__device__ unsigned g_krem2[BB];
__device__ unsigned g_thr[BB];
__device__ unsigned g_ctr1[BB];
__device__ unsigned g_ctr2[BB];
__device__ unsigned g_ccount[BB];
__device__ unsigned g_cand[BB*CAND_CAP];

// Order-preserving float <-> uint bijection (total order, strict monotone)
__device__ __forceinline__ unsigned f2o(float f){
    unsigned b = __float_as_uint(f);
    return (b & 0x80000000u) ? ~b : (b | 0x80000000u);
}

// ---------------------------------------------------------------- zero scratch
__global__ void k_zero(){
    int i = blockIdx.x*blockDim.x + threadIdx.x;
    int stride = gridDim.x*blockDim.x;
    for (int j = i; j < NSEG; j += stride) g_bm[j] = 0u;
    for (int j = i; j < BB*2048; j += stride){ g_h1[j] = 0u; g_h2[j] = 0u; }
    if (i < BB){ g_ctr1[i] = 0u; g_ctr2[i] = 0u; g_ccount[i] = 0u; }
}

// -------- pass A: seg ids + 32-bit block max (coalesced scalar per point)
__global__ void k_blockmax(const float* __restrict__ pred,
                           const int4*  __restrict__ coords){
    int i = blockIdx.x*blockDim.x + threadIdx.x;
    int stride = gridDim.x*blockDim.x;
    for (int j = i; j < NN; j += stride){
        int4 c = coords[j];   // (batch, x, y, z) — coalesced LDG.128
        unsigned local = (((unsigned)c.y >> 2) * GG + ((unsigned)c.z >> 2)) * GG
                         + ((unsigned)c.w >> 2);
        g_seg16[j] = (unsigned short)local;
        atomicMax(&g_bm[(unsigned)c.x * SEGB + local], f2o(pred[j]));
    }
}

// ---- pass B: winner bitmap (1 thread per 32-pt word, no mask atomics)
//      + corrected level-1 histogram (raw adds − per-seg subs, fused)
//      + per-batch last-block level-1 scan
__global__ void k_wmask(const float* __restrict__ pred,
                        const int* __restrict__ tnum){
    __shared__ unsigned sh[2048];
    __shared__ int isLast;
    for (int j = threadIdx.x; j < 2048; j += blockDim.x) sh[j] = 0u;
    __syncthreads();

    int b = blockIdx.y;
    int w = blockIdx.x*blockDim.x + threadIdx.x;   // word within batch
    const unsigned* bmb = g_bm + b * SEGB;
    if (w < WPB){
        long p0 = (long)b * MM + (long)w * 32;     // first point of this word
        const float4*  p4 = (const float4*)pred + (p0 >> 2);
        const ushort4* s4 = (const ushort4*)g_seg16 + (p0 >> 2);
        unsigned word = 0u;
        #pragma unroll
        for (int c = 0; c < 8; c++){               // 8 chunks of 4 points
            float4  p = p4[c];
            ushort4 s = s4[c];
            unsigned f0 = f2o(p.x), f1 = f2o(p.y), f2 = f2o(p.z), f3 = f2o(p.w);
            word |= (unsigned)(f0 == bmb[s.x]) << (c*4 + 0);
            word |= (unsigned)(f1 == bmb[s.y]) << (c*4 + 1);
            word |= (unsigned)(f2 == bmb[s.z]) << (c*4 + 2);
            word |= (unsigned)(f3 == bmb[s.w]) << (c*4 + 3);
            atomicAdd(&sh[f0 >> 21], 1u);
            atomicAdd(&sh[f1 >> 21], 1u);
            atomicAdd(&sh[f2 >> 21], 1u);
            atomicAdd(&sh[f3 >> 21], 1u);
        }
        g_mask[(long)b * WPB + w] = word;          // plain coalesced store
    }

    // correction slice: this block owns segs [x*SEGSLICE, ...) of this batch;
    // each nonempty seg's masked point leaves its bin (unsigned wrap OK)
    {
        int s0 = blockIdx.x * SEGSLICE;
        int s1 = min(s0 + SEGSLICE, SEGB);
        for (int i = s0 + threadIdx.x; i < s1; i += blockDim.x){
            unsigned v = __ldcg(&bmb[i]);
            if (v) atomicSub(&sh[v >> 21], 1u);
        }
    }
    __syncthreads();

    unsigned* gh = g_h1 + b*2048;
    for (int j = threadIdx.x; j < 2048; j += blockDim.x){
        unsigned c = sh[j];
        if (c) atomicAdd(&gh[j], c);               // wraparound-safe partial sums
    }
    __threadfence();
    if (threadIdx.x == 0)
        isLast = (atomicAdd(&g_ctr1[b], 1u) == (unsigned)(WBLK - 1));
    __syncthreads();
    if (!isLast) return;

    // ---- level-1 scan over corrected g_h1 -> prefix1 + krem1 ----
    __shared__ unsigned partial[256];
    __shared__ unsigned excl[256];
    unsigned loc[8];
    unsigned s = 0;
    #pragma unroll
    for (int j = 0; j < 8; j++){ loc[j] = __ldcg(&gh[threadIdx.x*8 + j]); s += loc[j]; }
    partial[threadIdx.x] = s;
    __syncthreads();
    if (threadIdx.x == 0){
        unsigned c = 0;
        for (int t = 0; t < 256; t++){ unsigned v = partial[t]; excl[t] = c; c += v; }
    }
    __syncthreads();
    unsigned krem = (unsigned)(MM - tnum[0]);
    unsigned cum = excl[threadIdx.x];
    #pragma unroll
    for (int j = 0; j < 8; j++){
        unsigned bin = threadIdx.x*8 + j;
        unsigned c = loc[j];
        if (cum < krem && cum + c >= krem){
            g_prefix1[b] = bin;
            g_krem1[b]   = krem - cum;
        }
        cum += c;
    }
}

// -- pass 2: prefix1-filtered level-2 hist + staged compaction + fused scan
__global__ void k_hist2(const float* __restrict__ pred){
    __shared__ unsigned sh[2048];
    __shared__ unsigned stage[PPB];
    __shared__ unsigned scount, sbase;
    __shared__ int isLast;
    for (int j = threadIdx.x; j < 2048; j += blockDim.x) sh[j] = 0u;
    if (threadIdx.x == 0) scount = 0u;
    __syncthreads();

    int b = blockIdx.y;
    unsigned p1 = g_prefix1[b];
    int start = blockIdx.x * PPB;
    long base = (long)b * MM + start;
    const float4* p4 = (const float4*)pred + (base >> 2);
    const unsigned* gw = g_mask + (base >> 5);
    int nv = min(PPB, MM - start) >> 2;

    for (int v = threadIdx.x; v < nv; v += blockDim.x){
        float4 pv = p4[v];
        unsigned nib = (__ldcg(&gw[v >> 3]) >> ((v & 7) * 4)) & 0xFu;
        unsigned fx = f2o(pv.x), fy = f2o(pv.y), fz = f2o(pv.z), fw = f2o(pv.w);
        if (!(nib & 1u) && (fx >> 21) == p1){ atomicAdd(&sh[(fx >> 10) & 2047u], 1u);
                                              stage[atomicAdd(&scount, 1u)] = fx; }
        if (!(nib & 2u) && (fy >> 21) == p1){ atomicAdd(&sh[(fy >> 10) & 2047u], 1u);
                                              stage[atomicAdd(&scount, 1u)] = fy; }
        if (!(nib & 4u) && (fz >> 21) == p1){ atomicAdd(&sh[(fz >> 10) & 2047u], 1u);
                                              stage[atomicAdd(&scount, 1u)] = fz; }
        if (!(nib & 8u) && (fw >> 21) == p1){ atomicAdd(&sh[(fw >> 10) & 2047u], 1u);
                                              stage[atomicAdd(&scount, 1u)] = fw; }
    }
    __syncthreads();

    // one global reservation per block, then coalesced candidate flush
    if (threadIdx.x == 0) sbase = atomicAdd(&g_ccount[b], scount);
    __syncthreads();
    unsigned* cand = g_cand + (size_t)b * CAND_CAP;
    for (unsigned i = threadIdx.x; i < scount; i += blockDim.x)
        __stcg(&cand[sbase + i], stage[i]);

    unsigned* gh = g_h2 + b*2048;
    for (int j = threadIdx.x; j < 2048; j += blockDim.x){
        unsigned c = sh[j];
        if (c) atomicAdd(&gh[j], c);
    }
    __threadfence();
    if (threadIdx.x == 0)
        isLast = (atomicAdd(&g_ctr2[b], 1u) == (unsigned)(NCHUNK - 1));
    __syncthreads();
    if (!isLast) return;

    // ---- level-2 scan over g_h2 -> prefix2 (22 bit) + krem2 ----
    __shared__ unsigned partial[256];
    __shared__ unsigned excl[256];
    unsigned loc[8];
    unsigned s = 0;
    #pragma unroll
    for (int j = 0; j < 8; j++){ loc[j] = __ldcg(&gh[threadIdx.x*8 + j]); s += loc[j]; }
    partial[threadIdx.x] = s;
    __syncthreads();
    if (threadIdx.x == 0){
        unsigned c = 0;
        for (int t = 0; t < 256; t++){ unsigned v = partial[t]; excl[t] = c; c += v; }
    }
    __syncthreads();
    unsigned krem = g_krem1[b];
    unsigned cum = excl[threadIdx.x];
    #pragma unroll
    for (int j = 0; j < 8; j++){
        unsigned bin = threadIdx.x*8 + j;
        unsigned c = loc[j];
        if (cum < krem && cum + c >= krem){
            g_prefix2[b] = (p1 << 11) | bin;
            g_krem2[b]   = krem - cum;
        }
        cum += c;
    }
}

// ------ pass D: candidates only (one block per batch), in-shared hist + scan
__global__ void k_hist3(){
    __shared__ unsigned sh[1024];
    __shared__ unsigned partial[256];
    __shared__ unsigned excl[256];
    int b = blockIdx.x;
    for (int j = threadIdx.x; j < 1024; j += blockDim.x) sh[j] = 0u;
    __syncthreads();

    unsigned p22 = g_prefix2[b];
    unsigned n = min(g_ccount[b], (unsigned)CAND_CAP);
    const unsigned* cand = g_cand + (size_t)b * CAND_CAP;
    for (unsigned i = threadIdx.x; i < n; i += blockDim.x){
        unsigned k = __ldcg(&cand[i]);
        if ((k >> 10) == p22) atomicAdd(&sh[k & 1023u], 1u);
    }
    __syncthreads();

    unsigned loc[4];
    unsigned s = 0;
    #pragma unroll
    for (int j = 0; j < 4; j++){ loc[j] = sh[threadIdx.x*4 + j]; s += loc[j]; }
    partial[threadIdx.x] = s;
    __syncthreads();
    if (threadIdx.x == 0){
        unsigned c = 0;
        for (int t = 0; t < 256; t++){ unsigned v = partial[t]; excl[t] = c; c += v; }
    }
    __syncthreads();
    unsigned krem = g_krem2[b];
    unsigned cum = excl[threadIdx.x];
    #pragma unroll
    for (int j = 0; j < 4; j++){
        unsigned bin = threadIdx.x*4 + j;
        unsigned c = loc[j];
        if (cum < krem && cum + c >= krem)
            g_thr[b] = (p22 << 10) | bin;      // kth-smallest key
        cum += c;
    }
}

// -------------------------------------------------------- final masked output
__global__ void k_out(const float* __restrict__ pred, float* __restrict__ out){
    int v = blockIdx.x*blockDim.x + threadIdx.x;   // vector index, NN/4 total
    if (v >= NN/4) return;
    int b = v / (MM/4);
    unsigned thr = g_thr[b];
    unsigned nib = (__ldcg(&g_mask[v >> 3]) >> ((v & 7) * 4)) & 0xFu;
    float4 p = ((const float4*)pred)[v];
    float4 o;
    o.x = ((nib & 1u) || f2o(p.x) > thr) ? p.x : 0.0f;
    o.y = ((nib & 2u) || f2o(p.y) > thr) ? p.y : 0.0f;
    o.z = ((nib & 4u) || f2o(p.z) > thr) ? p.z : 0.0f;
    o.w = ((nib & 8u) || f2o(p.w) > thr) ? p.w : 0.0f;
    __stcs(&((float4*)out)[v], o);
}

extern "C" void kernel_launch(void* const* d_in, const int* in_sizes, int n_in,
                              void* d_out, int out_size){
    const float* pred   = (const float*)d_in[0];
    const int4*  coords = (const int4*)d_in[1];
    const int*   tnum   = (const int*)d_in[2];
    float* out = (float*)d_out;

    k_zero<<<512, 256>>>();
    k_blockmax<<<(NN + 511)/512, 256>>>(pred, coords);

    dim3 gw(WBLK, BB);                             // 123 x 8 blocks
    k_wmask<<<gw, 256>>>(pred, tnum);

    dim3 gh(NCHUNK, BB);
    k_hist2<<<gh, 256>>>(pred);
    k_hist3<<<BB, 256>>>();
    k_out<<<(NN/4 + 255)/256, 256>>>(pred, out);
}